// round 7
// baseline (speedup 1.0000x reference)
#include <cuda_runtime.h>
#include <math.h>
#include <float.h>

// ---------------- problem constants ----------------
#define BS   16
#define TT   50
#define NA   3
#define NC   80
#define HH   76
#define WW   76
#define NCH  255
#define HW   (HH*WW)                              // 5776
#define CELLS_PER_B (NA*HW)                       // 17328
#define TPB  256
#define BLKS_PER_B ((CELLS_PER_B + TPB - 1)/TPB)  // 68
#define NBLK (BS*BLKS_PER_B)                      // 1088
#define FINF FLT_MAX

// bucket quantization of ln(area): 64 buckets of width 0.25 over [-8, 8]
#define BBASE  (-8.0f)
#define BINV   (4.0f)
#define LN_LO  (-0.6955f)   // < ln(0.499): conservative (IoU>=0.5 => ratio in [1/2,2])
#define LN_HI  ( 0.6955f)   // > ln(2.004)

// ---------------- device scratch (static, no allocations) ----------------
__device__ float    g_sla[BS][64];                // sorted ln(area), FINF-padded
__device__ float    g_sar[BS][64];                // sorted areas
__device__ float4   g_sbx[BS][64];                // sorted corners (x1,x2,y1,y2)
__device__ int      g_bst[BS][64];                // bucket -> first sorted idx
__device__ uint2    g_occ2[BS];                   // 64-bit bucket occupancy
__device__ int      g_tcell[BS][TT];              // owner cell within image or -1
__device__ int      g_tcl[BS][TT];                // class index
__device__ float    g_ttx[BS][TT], g_tty[BS][TT]; // targets tx, ty
__device__ float    g_ttw[BS][TT], g_tth[BS][TT]; // targets tw, th (log form)
__device__ float    g_tsc[BS][TT];                // scale
__device__ float    g_part[7*NBLK];               // per-block partial sums
__device__ float    g_nobj_part[BS];              // per-image valid counts
__device__ unsigned g_count;                      // completion ticket (self-resetting)

// scaled anchors (TOTAL / STRIDE=8)
__constant__ float c_staw[9] = {1.25f, 2.0f, 4.125f, 3.75f, 7.75f, 7.375f, 14.5f, 19.5f, 46.625f};
__constant__ float c_stah[9] = {1.625f, 3.75f, 2.875f, 7.625f, 5.625f, 14.875f, 11.25f, 24.75f, 40.75f};
__constant__ float c_saw[3]  = {1.25f, 2.0f, 4.125f};
__constant__ float c_sah[3]  = {1.625f, 3.75f, 2.875f};
__constant__ float c_lapq[3] = {0.7086512f, 2.0149030f, 2.4731199f};  // ln(saw*sah)

// ---------------- helpers ----------------
__device__ __forceinline__ float softplus(float z) {          // == bce(sigmoid(z), 0)
    return __logf(1.0f + __expf(z));
}
__device__ __forceinline__ float sigm(float z) {
    return __fdividef(1.0f, 1.0f + __expf(-z));
}
__device__ __forceinline__ float safelog(float p) { return p > 0.f ? __logf(p) : -100.0f; }
__device__ __forceinline__ float bce(float p, float t) {
    return -(t * safelog(p) + (1.f - t) * safelog(1.f - p));
}
__device__ __forceinline__ float sl1(float p, float t) {
    float d = fabsf(p - t);
    return d < 1.f ? 0.5f * d * d : d - 0.5f;
}
__device__ __forceinline__ int bucket_of(float la) {
    int k = (int)((la - BBASE) * BINV);
    return min(max(k, 0), 63);
}

// ---------------- kernel A: per-image prep (16 blocks x 64 threads) ----------------
__global__ void __launch_bounds__(64) prep_kernel(const float* __restrict__ tgt) {
    __shared__ float    s_areaT[TT];
    __shared__ int      s_braw[64];
    __shared__ unsigned s_oc[2];
    int b = blockIdx.x, tid = threadIdx.x;

    s_braw[tid] = 64;
    if (tid < 2) s_oc[tid] = 0u;

    float area = FINF, larea = FINF, x1 = 0.f, x2 = 0.f, y1 = 0.f, y2 = 0.f;
    int valid = 0, cell = -1;
    if (tid < TT) {
        const float* p = tgt + (size_t)(b * TT + tid) * 5;
        float t0 = p[0], t1 = p[1], t2 = p[2], t3 = p[3], t4 = p[4];
        valid = ((t0 + t1 + t2 + t3 + t4) != 0.f) ? 1 : 0;
        float gx = t1 * (float)WW, gy = t2 * (float)HH;
        float gw = t3 * (float)WW, gh = t4 * (float)HH;
        int gi = (int)gx, gj = (int)gy;

        // anchor match vs 9 total scaled anchors; first-max argmax
        float ga = gw * gh;
        float best = -1e30f; int bestn = 0;
#pragma unroll
        for (int n = 0; n < 9; n++) {
            float inter = fminf(gw, c_staw[n]) * fminf(gh, c_stah[n]);
            float v = inter / (ga + c_staw[n] * c_stah[n] - inter + 1e-16f);
            if (v > best) { best = v; bestn = n; }
        }
        int wr = (valid && bestn < 3) ? bestn : -1;

        x1 = gx - gw * 0.5f; x2 = gx + gw * 0.5f;
        y1 = gy - gh * 0.5f; y2 = gy + gh * 0.5f;
        if (valid) {
            area  = (x2 - x1) * (y2 - y1);
            larea = __logf(area);
        }
        s_areaT[tid] = area;
        g_tcl[b][tid] = (int)t0;
        if (wr >= 0) {
            g_ttx[b][tid] = gx - (float)gi;
            g_tty[b][tid] = gy - (float)gj;
            g_ttw[b][tid] = logf(gw / c_saw[wr] + 1e-16f);
            g_tth[b][tid] = logf(gh / c_sah[wr] + 1e-16f);
            g_tsc[b][tid] = 2.0f - t3 * t4;
            cell = wr * HW + gj * WW + gi;
        }
        g_tcell[b][tid] = cell;
    }
    int nobj = __syncthreads_count(tid < TT && valid);
    if (tid == 0) g_nobj_part[b] = (float)nobj;

    // rank sort (stable by index) + bucket marks
    if (tid < TT) {
        int rank = 0;
        for (int j = 0; j < TT; j++) {
            float aj = s_areaT[j];
            rank += (aj < area) || (aj == area && j < tid);
        }
        g_sla[b][rank] = larea;
        g_sar[b][rank] = area;
        g_sbx[b][rank] = make_float4(x1, x2, y1, y2);
        if (valid) {
            int bk = bucket_of(larea);
            atomicMin(&s_braw[bk], rank);
            atomicOr(&s_oc[bk >> 5], 1u << (bk & 31));
        }
    } else {
        g_sla[b][tid] = FINF;
        g_sar[b][tid] = FINF;
    }
    __syncthreads();

    // suffix-min -> bucket start table
    int m = 64;
    for (int j = tid; j < 64; j++) m = min(m, s_braw[j]);
    g_bst[b][tid] = m;
    if (tid == 0) g_occ2[b] = make_uint2(s_oc[0], s_oc[1]);
}

// ---------------- kernel B: per-cell loss ----------------
__global__ void __launch_bounds__(TPB) yolo_kernel(const float* __restrict__ inp,
                                                   float* __restrict__ out) {
    __shared__ float    s_la[64];
    __shared__ float    s_ar[64];
    __shared__ float4   s_sbox[64];
    __shared__ int      s_bst[64];
    __shared__ float    s_tx[TT], s_ty[TT], s_tw[TT], s_th[TT], s_sc[TT];
    __shared__ int      s_tcell[TT], s_tcl[TT];
    __shared__ int      s_owner[TPB];
    __shared__ unsigned s_oc[2];
    __shared__ float    s_acc[7];
    __shared__ float    s_nobj;
    __shared__ unsigned s_ticket;
    __shared__ double   s_sum[7];

    int tid = threadIdx.x;
    int b   = blockIdx.x / BLKS_PER_B;
    int c0  = (blockIdx.x % BLKS_PER_B) * TPB;

    // ---- prefix: clear + coalesced loads of precomputed tables ----
    s_owner[tid] = 0;
    if (tid < 7)  s_acc[tid] = 0.f;
    if (tid < 64) {
        s_la[tid]   = g_sla[b][tid];
        s_ar[tid]   = g_sar[b][tid];
        s_sbox[tid] = g_sbx[b][tid];
        s_bst[tid]  = g_bst[b][tid];
    }
    if (tid < 2) s_oc[tid] = tid ? g_occ2[b].y : g_occ2[b].x;
    int cell = -1;
    if (tid < TT) {
        cell = g_tcell[b][tid];
        s_tcell[tid] = cell;
        s_tcl[tid]   = g_tcl[b][tid];
        s_tx[tid] = g_ttx[b][tid];  s_ty[tid] = g_tty[b][tid];
        s_tw[tid] = g_ttw[b][tid];  s_th[tid] = g_tth[b][tid];
        s_sc[tid] = g_tsc[b][tid];
    }
    __syncthreads();                              // owner clear + cell loads done
    if (cell >= c0 && cell < c0 + TPB)            // last-writer-wins scatter
        atomicMax(&s_owner[cell - c0], tid + 1);
    __syncthreads();

    unsigned occ0 = s_oc[0], occ1 = s_oc[1];

    // ---- per-cell loss ----
    float v0 = 0.f, v1 = 0.f, v2 = 0.f, v3 = 0.f, v4 = 0.f, v5 = 0.f, v6 = 0.f;
    bool rare = false;
    int local = c0 + tid;

    if (local < CELLS_PER_B) {
        int a = local / HW;
        int r = local - a * HW;
        int j = r / WW;
        int i = r - j * WW;

        const float* base = inp + (size_t)(b * NCH + a * 85) * HW + r;
        float wv = base[2*HW];
        float hv = base[3*HW];
        float zc = base[4*HW];
        int owner = s_owner[tid];

        if (owner) {
            // ------ rare: this cell owns a target ------
            rare = true;
            int g = owner - 1;
            float sx = sigm(base[0]);
            float sy = sigm(base[HW]);
            float sc = s_sc[g];
            v0 = sc * bce(sx, s_tx[g]);
            v1 = sc * bce(sy, s_ty[g]);
            v2 = sc * sl1(wv, s_tw[g]);
            v3 = sc * sl1(hv, s_th[g]);
            v4 = softplus(-zc);                           // bce(conf, 1)
            // class bitmask: scan targets that write this cell
            unsigned m0 = 0, m1 = 0, m2 = 0;
            for (int t = 0; t < TT; t++) {
                if (s_tcell[t] == local) {
                    int c = s_tcl[t];
                    if (c < 32)      m0 |= 1u << c;
                    else if (c < 64) m1 |= 1u << (c - 32);
                    else             m2 |= 1u << (c - 64);
                }
            }
            float s = 0.f;
            for (int c = 0; c < NC; c++) {
                float z = base[(5 + c) * HW];
                unsigned bit = ((c < 32) ? (m0 >> c)
                              : (c < 64) ? (m1 >> (c - 32))
                                         : (m2 >> (c - 64))) & 1u;
                s += softplus(bit ? -z : z);
            }
            v6 = s;
        } else {
            // ------ common: register-only bucket occupancy prefilter ------
            float lpa = wv + hv + c_lapq[a];              // ln(pred area)
            float lU  = lpa + LN_HI;
            int bl = bucket_of(lpa + LN_LO);
            int bu = bucket_of(lU);
            unsigned long long occ = ((unsigned long long)occ1 << 32) | occ0;
            unsigned long long wm = ((bu >= 63) ? ~0ull : ((1ull << (bu + 1)) - 1ull))
                                    & ~((1ull << bl) - 1ull);
            bool ign = false;
            if (occ & wm) {
                int lo = s_bst[bl];
                float sx = sigm(base[0]);
                float sy = sigm(base[HW]);
                float pw = __expf(wv) * c_saw[a];
                float ph = __expf(hv) * c_sah[a];
                float px = sx + (float)i, py = sy + (float)j;
                float px1 = px - pw * 0.5f, px2 = px + pw * 0.5f;
                float py1 = py - ph * 0.5f, py2 = py + ph * 0.5f;
                float pa2 = (px2 - px1) * (py2 - py1);
                for (int idx = lo; idx < 64; idx++) {
                    if (s_la[idx] > lU) break;            // sorted: no later candidates
                    float4 tb = s_sbox[idx];
                    float iw = fmaxf(fminf(px2, tb.y) - fmaxf(px1, tb.x), 0.f);
                    float ih = fmaxf(fminf(py2, tb.w) - fmaxf(py1, tb.z), 0.f);
                    float inter = iw * ih;
                    float iou = __fdividef(inter, s_ar[idx] + pa2 - inter + 1e-16f);
                    if (iou >= 0.5f) { ign = true; break; }
                }
            }
            if (!ign) v5 = softplus(zc);                  // bce(conf, 0)
        }
    }

    // ---- block reduction ----
    unsigned full = 0xffffffffu;
    unsigned anyrare = __ballot_sync(full, rare);
#pragma unroll
    for (int o = 16; o; o >>= 1) v5 += __shfl_down_sync(full, v5, o);
    if (anyrare) {
#pragma unroll
        for (int o = 16; o; o >>= 1) {
            v0 += __shfl_down_sync(full, v0, o);
            v1 += __shfl_down_sync(full, v1, o);
            v2 += __shfl_down_sync(full, v2, o);
            v3 += __shfl_down_sync(full, v3, o);
            v4 += __shfl_down_sync(full, v4, o);
            v6 += __shfl_down_sync(full, v6, o);
        }
    }
    if ((tid & 31) == 0) {
        atomicAdd(&s_acc[5], v5);
        if (anyrare) {
            atomicAdd(&s_acc[0], v0);
            atomicAdd(&s_acc[1], v1);
            atomicAdd(&s_acc[2], v2);
            atomicAdd(&s_acc[3], v3);
            atomicAdd(&s_acc[4], v4);
            atomicAdd(&s_acc[6], v6);
        }
    }
    __syncthreads();
    if (tid < 7) g_part[tid * NBLK + blockIdx.x] = s_acc[tid];

    // ---- last block finalizes ----
    __threadfence();
    if (tid == 0) s_ticket = atomicAdd(&g_count, 1u);
    __syncthreads();
    if (s_ticket == NBLK - 1) {
        __threadfence();
        int w = tid >> 5, lane = tid & 31;
        if (w < 7) {
            double s = 0.0;
            for (int k = lane; k < NBLK; k += 32) s += (double)g_part[w * NBLK + k];
#pragma unroll
            for (int o = 16; o; o >>= 1) s += __shfl_down_sync(full, s, o);
            if (lane == 0) s_sum[w] = s;
        } else if (w == 7) {
            float nv = (lane < BS) ? g_nobj_part[lane] : 0.f;
#pragma unroll
            for (int o = 16; o; o >>= 1) nv += __shfl_down_sync(full, nv, o);
            if (lane == 0) s_nobj = nv;
        }
        __syncthreads();
        if (tid == 0) {
            g_count = 0;                                   // reset for next graph replay
            double n = (double)s_nobj;
            double lx = s_sum[0] / n, ly = s_sum[1] / n;
            double lw = s_sum[2] / n, lh = s_sum[3] / n;
            double lconf = s_sum[4] / n + 0.5 * (s_sum[5] / n);
            double lcls  = s_sum[6] / n;
            out[0] = (float)(2.5 * (lx + ly) + 2.5 * (lw + lh) + lconf + lcls);
            out[1] = (float)lx;
            out[2] = (float)ly;
            out[3] = (float)lw;
            out[4] = (float)lh;
            out[5] = (float)lconf;
            out[6] = (float)lcls;
        }
    }
}

// ---------------- launch ----------------
extern "C" void kernel_launch(void* const* d_in, const int* in_sizes, int n_in,
                              void* d_out, int out_size) {
    const float* inp = (const float*)d_in[0];
    const float* tgt = (const float*)d_in[1];
    if (n_in >= 2 && in_sizes[0] == BS * TT * 5) {   // identify tensors by size
        const float* tmp = inp; inp = tgt; tgt = tmp;
    }
    float* out = (float*)d_out;

    prep_kernel<<<BS, 64>>>(tgt);
    yolo_kernel<<<NBLK, TPB>>>(inp, out);
}